// round 12
// baseline (speedup 1.0000x reference)
#include <cuda_runtime.h>
#include <cuda_bf16.h>
#include <math.h>
#include <stdint.h>

#define MTOK 8192
#define DDIM 1024
#define HDIM 4096
#define NCB  8
#define KCB  256

#define K1C (3 * DDIM)    // 3072  concat-K of GEMM1
#define K2C (3 * HDIM)    // 12288 concat-K of GEMM2

// concat operand arrays (A-side layout [hi|lo|hi], B-side layout [hi|hi|lo])
__device__ __nv_bfloat16 g_xcat [(size_t)MTOK * K1C];   // 48 MB
__device__ __nv_bfloat16 g_w1cat[(size_t)HDIM * K1C];   // 25 MB
__device__ __nv_bfloat16 g_hcat [(size_t)MTOK * K2C];   // 192 MB
__device__ __nv_bfloat16 g_w2cat[(size_t)DDIM * K2C];   // 24 MB

// ---------------------------------------------------------------------------
__device__ __forceinline__ uint32_t smem_u32(const void* p) {
    uint32_t a;
    asm("{ .reg .u64 t; cvta.to.shared.u64 t, %1; cvt.u32.u64 %0, t; }"
        : "=r"(a) : "l"(p));
    return a;
}

#define CP_ASYNC16(dst, src) \
    asm volatile("cp.async.cg.shared.global [%0], [%1], 16;" \
        :: "r"(dst), "l"(src) : "memory")
#define CP_COMMIT() asm volatile("cp.async.commit_group;" ::: "memory")
#define CP_WAIT2()  asm volatile("cp.async.wait_group 2;"  ::: "memory")

#define LDSM_X4(r0, r1, r2, r3, a) \
    asm volatile("ldmatrix.sync.aligned.m8n8.x4.shared.b16 {%0,%1,%2,%3}, [%4];" \
        : "=r"(r0), "=r"(r1), "=r"(r2), "=r"(r3) : "r"(a))

#define MMA_BF16(c, a, b0, b1) \
    asm volatile("mma.sync.aligned.m16n8k16.row.col.f32.bf16.bf16.f32 " \
        "{%0,%1,%2,%3}, {%4,%5,%6,%7}, {%8,%9}, {%0,%1,%2,%3};" \
        : "+f"((c)[0]), "+f"((c)[1]), "+f"((c)[2]), "+f"((c)[3]) \
        : "r"((a)[0]), "r"((a)[1]), "r"((a)[2]), "r"((a)[3]), "r"(b0), "r"(b1))

// ---------------------------------------------------------------------------
// Pre-pass kernels: build concat operands
// ---------------------------------------------------------------------------
__device__ __forceinline__ void split4(float4 v, uint32_t& hi0, uint32_t& hi1,
                                       uint32_t& lo0, uint32_t& lo1) {
    __nv_bfloat162 h01 = __floats2bfloat162_rn(v.x, v.y);
    __nv_bfloat162 h23 = __floats2bfloat162_rn(v.z, v.w);
    __nv_bfloat162 l01 = __floats2bfloat162_rn(v.x - __bfloat162float(h01.x),
                                               v.y - __bfloat162float(h01.y));
    __nv_bfloat162 l23 = __floats2bfloat162_rn(v.z - __bfloat162float(h23.x),
                                               v.w - __bfloat162float(h23.y));
    memcpy(&hi0, &h01, 4); memcpy(&hi1, &h23, 4);
    memcpy(&lo0, &l01, 4); memcpy(&lo1, &l23, 4);
}

// A-side: [hi | lo | hi]
__global__ void split_x_cat(const float* __restrict__ x,
                            __nv_bfloat16* __restrict__ xc, int n4, int Kd) {
    int i = blockIdx.x * blockDim.x + threadIdx.x;
    if (i >= n4) return;
    const int pr4 = Kd >> 2;
    int row = i / pr4;
    int col = (i - row * pr4) << 2;
    float4 v = reinterpret_cast<const float4*>(x)[i];
    uint32_t h0, h1, l0, l1;
    split4(v, h0, h1, l0, l1);
    __nv_bfloat16* base = xc + (size_t)row * (3 * Kd) + col;
    *reinterpret_cast<uint2*>(base)          = make_uint2(h0, h1);
    *reinterpret_cast<uint2*>(base + Kd)     = make_uint2(l0, l1);
    *reinterpret_cast<uint2*>(base + 2 * Kd) = make_uint2(h0, h1);
}

// B-side: [hi | hi | lo]
__global__ void dequant_cat(const float* __restrict__ cb,
                            const int*   __restrict__ idx,
                            __nv_bfloat16* __restrict__ Wc,
                            int rows, int sub) {
    const int Kd = NCB * sub;
    const int per_row4 = Kd >> 2;
    int tid = blockIdx.x * blockDim.x + threadIdx.x;
    if (tid >= rows * per_row4) return;
    int row = tid / per_row4;
    int col = (tid - row * per_row4) << 2;
    int c   = col / sub;
    int j   = col - c * sub;
    int code = __ldg(&idx[c * rows + row]);
    float4 v = *reinterpret_cast<const float4*>(cb + ((size_t)(c * KCB + code)) * sub + j);
    uint32_t h0, h1, l0, l1;
    split4(v, h0, h1, l0, l1);
    __nv_bfloat16* base = Wc + (size_t)row * (3 * Kd) + col;
    *reinterpret_cast<uint2*>(base)          = make_uint2(h0, h1);
    *reinterpret_cast<uint2*>(base + Kd)     = make_uint2(h0, h1);
    *reinterpret_cast<uint2*>(base + 2 * Kd) = make_uint2(l0, l1);
}

// ---------------------------------------------------------------------------
// Single-operand-pair bf16 mma.sync GEMM over concat-K.
// C[m,n] = sum_k A[m,k]*B[n,k] (+bias, opt GELU).
// CTA 128x256, BK=64, 4-stage cp.async pipeline, 256 threads, warp 64x64.
// Full A/B fragment double-buffering in registers.
// ---------------------------------------------------------------------------
#define BM 128
#define BN 256
#define BKE 64
#define TILE_A  (BM * BKE * 2)                 // 16 KB
#define TILE_BB (BN * BKE * 2)                 // 32 KB
#define STAGE_B (TILE_A + TILE_BB)             // 48 KB
#define NSTAGE  4
#define SMEM_TOT (NSTAGE * STAGE_B)            // 192 KB

__device__ __forceinline__ void load_stage(uint32_t stage,
    const __nv_bfloat16* __restrict__ A, const __nv_bfloat16* __restrict__ B,
    int bm, int bn, int k0, int K, int tid)
{
    const int row = tid >> 1;            // 0..127
    const int kc0 = (tid & 1) * 4;       // 16B-chunk 0..7
    const uint32_t sw = ((uint32_t)(row & 7)) << 4;
    const uint32_t rb = (uint32_t)row * 128;
    const uint32_t sA = stage;
    const uint32_t sB = stage + TILE_A;

    const __nv_bfloat16* pA = A + (size_t)(bm + row) * K + k0;
    #pragma unroll
    for (int i = 0; i < 4; i++) {
        int kc = kc0 + i;
        CP_ASYNC16(sA + rb + (((uint32_t)kc * 16) ^ sw), pA + kc * 8);
    }
    #pragma unroll
    for (int g = 0; g < 2; g++) {
        int brow = row + g * 128;
        const __nv_bfloat16* pB = B + (size_t)(bn + brow) * K + k0;
        uint32_t brb = (uint32_t)brow * 128;
        #pragma unroll
        for (int i = 0; i < 4; i++) {
            int kc = kc0 + i;
            CP_ASYNC16(sB + brb + (((uint32_t)kc * 16) ^ sw), pB + kc * 8);
        }
    }
}

template<bool GELU, bool OUT_SPLIT>
__global__ __launch_bounds__(256, 1)
void gemm_cat(const __nv_bfloat16* __restrict__ A, const __nv_bfloat16* __restrict__ B,
              const float* __restrict__ bias,
              float* __restrict__ Cf,                 // !OUT_SPLIT: fp32 out, ld=N
              __nv_bfloat16* __restrict__ Hc,         // OUT_SPLIT: concat out, ld=3N
              int M, int N, int K)
{
    extern __shared__ __align__(1024) char smem[];
    const uint32_t sb = smem_u32(smem);
    const int tid  = threadIdx.x;
    const int wid  = tid >> 5;
    const int lane = tid & 31;
    const int wr   = wid & 1;          // warp m-tile (64 rows)
    const int wc   = wid >> 1;         // warp n-tile (64 cols)
    const int bm   = blockIdx.y * BM;
    const int bn   = blockIdx.x * BN;

    float acc[4][8][4];
    #pragma unroll
    for (int a = 0; a < 4; a++)
        #pragma unroll
        for (int b = 0; b < 8; b++)
            #pragma unroll
            for (int c = 0; c < 4; c++) acc[a][b][c] = 0.0f;

    // ldmatrix lane addressing
    const int amat = lane >> 3, ar = lane & 7;
    const int a_m  = wr * 64 + (amat & 1) * 8 + ar;
    const uint32_t a_kh = (uint32_t)(amat >> 1) * 16;
    const uint32_t a_rb = (uint32_t)a_m * 128;
    const uint32_t a_sx = ((uint32_t)(a_m & 7)) << 4;

    const int bmat = lane >> 3, br = lane & 7;
    const int b_n  = wc * 64 + ((bmat >> 1) << 3) + br;
    const uint32_t b_kh = (uint32_t)(bmat & 1) * 16;
    const uint32_t b_rb = (uint32_t)b_n * 128;
    const uint32_t b_sx = ((uint32_t)(b_n & 7)) << 4;

    const int NT = K / BKE;

    // prologue: prefetch 3 stages
    #pragma unroll
    for (int s = 0; s < NSTAGE - 1; s++) {
        load_stage(sb + s * STAGE_B, A, B, bm, bn, s * BKE, K, tid);
        CP_COMMIT();
    }

    for (int it = 0; it < NT; it++) {
        CP_WAIT2();
        __syncthreads();

        int pf = it + NSTAGE - 1;
        if (pf < NT)
            load_stage(sb + (pf & (NSTAGE - 1)) * STAGE_B, A, B,
                       bm, bn, pf * BKE, K, tid);
        CP_COMMIT();   // always commit to keep wait_group arithmetic exact

        const uint32_t st = sb + (it & (NSTAGE - 1)) * STAGE_B;
        const uint32_t sA = st;
        const uint32_t sB = st + TILE_A;

        uint32_t af[2][4][4];
        uint32_t bf[2][4];

        // preload kk=0 A frags and (0,0) B frag
        #pragma unroll
        for (int mt = 0; mt < 4; mt++) {
            uint32_t off = a_rb + mt * 2048 + (a_kh ^ a_sx);
            LDSM_X4(af[0][mt][0], af[0][mt][1], af[0][mt][2], af[0][mt][3], sA + off);
        }
        {
            uint32_t off = b_rb + (b_kh ^ b_sx);
            LDSM_X4(bf[0][0], bf[0][1], bf[0][2], bf[0][3], sB + off);
        }

        #pragma unroll
        for (int kk = 0; kk < 4; kk++) {
            const int ab = kk & 1;
            #pragma unroll
            for (int pr = 0; pr < 4; pr++) {
                const int bb = (kk * 4 + pr) & 1;
                // prefetch next B fragment
                if (pr < 3) {
                    uint32_t off = b_rb + (pr + 1) * 2048
                                 + (((uint32_t)kk * 32 + b_kh) ^ b_sx);
                    LDSM_X4(bf[bb ^ 1][0], bf[bb ^ 1][1], bf[bb ^ 1][2], bf[bb ^ 1][3],
                            sB + off);
                } else if (kk < 3) {
                    uint32_t off = b_rb + (((uint32_t)(kk + 1) * 32 + b_kh) ^ b_sx);
                    LDSM_X4(bf[bb ^ 1][0], bf[bb ^ 1][1], bf[bb ^ 1][2], bf[bb ^ 1][3],
                            sB + off);
                }
                // prefetch next kk's A fragments mid-stream
                if (pr == 2 && kk < 3) {
                    #pragma unroll
                    for (int mt = 0; mt < 4; mt++) {
                        uint32_t off = a_rb + mt * 2048
                                     + (((uint32_t)(kk + 1) * 32 + a_kh) ^ a_sx);
                        LDSM_X4(af[ab ^ 1][mt][0], af[ab ^ 1][mt][1],
                                af[ab ^ 1][mt][2], af[ab ^ 1][mt][3], sA + off);
                    }
                }
                #pragma unroll
                for (int mt = 0; mt < 4; mt++) {
                    MMA_BF16(acc[mt][pr * 2 + 0], af[ab][mt], bf[bb][0], bf[bb][1]);
                    MMA_BF16(acc[mt][pr * 2 + 1], af[ab][mt], bf[bb][2], bf[bb][3]);
                }
            }
        }
    }

    // epilogue
    const int mrow = bm + wr * 64 + (lane >> 2);
    const int ncol = bn + wc * 64 + (lane & 3) * 2;
    const int ldh  = 3 * N;
    #pragma unroll
    for (int mt = 0; mt < 4; mt++) {
        #pragma unroll
        for (int n8 = 0; n8 < 8; n8++) {
            const int n = ncol + n8 * 8;
            const float bs0 = __ldg(&bias[n]);
            const float bs1 = __ldg(&bias[n + 1]);
            #pragma unroll
            for (int hf = 0; hf < 2; hf++) {
                const int m = mrow + mt * 16 + hf * 8;
                float v0 = acc[mt][n8][hf * 2 + 0] + bs0;
                float v1 = acc[mt][n8][hf * 2 + 1] + bs1;
                if (GELU) {
                    v0 = 0.5f * v0 * (1.0f + erff(v0 * 0.70710678118654752440f));
                    v1 = 0.5f * v1 * (1.0f + erff(v1 * 0.70710678118654752440f));
                }
                if (OUT_SPLIT) {
                    __nv_bfloat162 h2 = __floats2bfloat162_rn(v0, v1);
                    __nv_bfloat162 l2 = __floats2bfloat162_rn(
                        v0 - __bfloat162float(h2.x), v1 - __bfloat162float(h2.y));
                    __nv_bfloat16* base = Hc + (size_t)m * ldh + n;
                    *reinterpret_cast<__nv_bfloat162*>(base)         = h2;   // slice0 hi
                    *reinterpret_cast<__nv_bfloat162*>(base + N)     = l2;   // slice1 lo
                    *reinterpret_cast<__nv_bfloat162*>(base + 2 * N) = h2;   // slice2 hi
                } else {
                    *reinterpret_cast<float2*>(Cf + (size_t)m * N + n) = make_float2(v0, v1);
                }
            }
        }
    }
}

// ---------------------------------------------------------------------------
extern "C" void kernel_launch(void* const* d_in, const int* in_sizes, int n_in,
                              void* d_out, int out_size) {
    const float* x    = (const float*)d_in[0];
    const float* cb1  = (const float*)d_in[1];
    const int*   idx1 = (const int*)  d_in[2];
    const float* b1   = (const float*)d_in[3];
    const float* cb2  = (const float*)d_in[4];
    const int*   idx2 = (const int*)  d_in[5];
    const float* b2   = (const float*)d_in[6];
    float* out = (float*)d_out;

    __nv_bfloat16 *xc, *w1c, *hc, *w2c;
    cudaGetSymbolAddress((void**)&xc,  g_xcat);
    cudaGetSymbolAddress((void**)&w1c, g_w1cat);
    cudaGetSymbolAddress((void**)&hc,  g_hcat);
    cudaGetSymbolAddress((void**)&w2c, g_w2cat);

    cudaFuncSetAttribute(gemm_cat<true, true>,
                         cudaFuncAttributeMaxDynamicSharedMemorySize, SMEM_TOT);
    cudaFuncSetAttribute(gemm_cat<false, false>,
                         cudaFuncAttributeMaxDynamicSharedMemorySize, SMEM_TOT);

    // pre-passes
    {
        int n4 = (MTOK * DDIM) / 4;
        split_x_cat<<<(n4 + 255) / 256, 256>>>(x, xc, n4, DDIM);
    }
    {
        int n = HDIM * (DDIM / 4);
        dequant_cat<<<(n + 255) / 256, 256>>>(cb1, idx1, w1c, HDIM, DDIM / NCB);
    }
    {
        int n = DDIM * (HDIM / 4);
        dequant_cat<<<(n + 255) / 256, 256>>>(cb2, idx2, w2c, DDIM, HDIM / NCB);
    }

    // GEMM1: hcat = gelu(x @ W1^T + b1) as [hi|lo|hi] concat rows
    {
        dim3 grid(HDIM / BN, MTOK / BM);     // (16, 64)
        gemm_cat<true, true><<<grid, 256, SMEM_TOT>>>(
            xc, w1c, b1, nullptr, hc, MTOK, HDIM, K1C);
    }
    // GEMM2: out = h @ W2^T + b2 (fp32)
    {
        dim3 grid(DDIM / BN, MTOK / BM);     // (4, 64)
        gemm_cat<false, false><<<grid, 256, SMEM_TOT>>>(
            hc, w2c, b2, out, nullptr, MTOK, DDIM, K2C);
    }
}

// round 13
// speedup vs baseline: 1.3219x; 1.3219x over previous
#include <cuda_runtime.h>
#include <cuda_bf16.h>
#include <math.h>
#include <stdint.h>

#define MTOK 8192
#define DDIM 1024
#define HDIM 4096
#define NCB  8
#define KCB  256

__device__ __nv_bfloat16 g_xhi [(size_t)MTOK * DDIM];
__device__ __nv_bfloat16 g_xlo [(size_t)MTOK * DDIM];
__device__ __nv_bfloat16 g_w1hi[(size_t)HDIM * DDIM];
__device__ __nv_bfloat16 g_w1lo[(size_t)HDIM * DDIM];
__device__ __nv_bfloat16 g_w2hi[(size_t)DDIM * HDIM];
__device__ __nv_bfloat16 g_w2lo[(size_t)DDIM * HDIM];
__device__ __nv_bfloat16 g_hhi [(size_t)MTOK * HDIM];
__device__ __nv_bfloat16 g_hlo [(size_t)MTOK * HDIM];

// ---------------------------------------------------------------------------
__device__ __forceinline__ uint32_t smem_u32(const void* p) {
    uint32_t a;
    asm("{ .reg .u64 t; cvta.to.shared.u64 t, %1; cvt.u32.u64 %0, t; }"
        : "=r"(a) : "l"(p));
    return a;
}

#define CP_ASYNC16(dst, src) \
    asm volatile("cp.async.cg.shared.global [%0], [%1], 16;" \
        :: "r"(dst), "l"(src) : "memory")
#define CP_COMMIT() asm volatile("cp.async.commit_group;" ::: "memory")
#define CP_WAIT0()  asm volatile("cp.async.wait_group 0;"  ::: "memory")

#define LDSM_X4(r0, r1, r2, r3, a) \
    asm volatile("ldmatrix.sync.aligned.m8n8.x4.shared.b16 {%0,%1,%2,%3}, [%4];" \
        : "=r"(r0), "=r"(r1), "=r"(r2), "=r"(r3) : "r"(a))

#define MMA_BF16(c, a, b0, b1) \
    asm volatile("mma.sync.aligned.m16n8k16.row.col.f32.bf16.bf16.f32 " \
        "{%0,%1,%2,%3}, {%4,%5,%6,%7}, {%8,%9}, {%0,%1,%2,%3};" \
        : "+f"((c)[0]), "+f"((c)[1]), "+f"((c)[2]), "+f"((c)[3]) \
        : "r"((a)[0]), "r"((a)[1]), "r"((a)[2]), "r"((a)[3]), "r"(b0), "r"(b1))

// ---------------------------------------------------------------------------
// Pre-pass kernels
// ---------------------------------------------------------------------------
__device__ __forceinline__ void split4(float4 v, uint32_t& hi0, uint32_t& hi1,
                                       uint32_t& lo0, uint32_t& lo1) {
    __nv_bfloat162 h01 = __floats2bfloat162_rn(v.x, v.y);
    __nv_bfloat162 h23 = __floats2bfloat162_rn(v.z, v.w);
    __nv_bfloat162 l01 = __floats2bfloat162_rn(v.x - __bfloat162float(h01.x),
                                               v.y - __bfloat162float(h01.y));
    __nv_bfloat162 l23 = __floats2bfloat162_rn(v.z - __bfloat162float(h23.x),
                                               v.w - __bfloat162float(h23.y));
    memcpy(&hi0, &h01, 4); memcpy(&hi1, &h23, 4);
    memcpy(&lo0, &l01, 4); memcpy(&lo1, &l23, 4);
}

__global__ void split_x_kernel(const float* __restrict__ x,
                               __nv_bfloat16* __restrict__ xhi,
                               __nv_bfloat16* __restrict__ xlo, int n4) {
    int i = blockIdx.x * blockDim.x + threadIdx.x;
    if (i >= n4) return;
    float4 v = reinterpret_cast<const float4*>(x)[i];
    uint32_t h0, h1, l0, l1;
    split4(v, h0, h1, l0, l1);
    reinterpret_cast<uint2*>(xhi)[i] = make_uint2(h0, h1);
    reinterpret_cast<uint2*>(xlo)[i] = make_uint2(l0, l1);
}

__global__ void dequant_split_kernel(const float* __restrict__ cb,
                                     const int*   __restrict__ idx,
                                     __nv_bfloat16* __restrict__ Whi,
                                     __nv_bfloat16* __restrict__ Wlo,
                                     int rows, int sub) {
    const int per_row4 = (NCB * sub) >> 2;
    int tid = blockIdx.x * blockDim.x + threadIdx.x;
    if (tid >= rows * per_row4) return;
    int row = tid / per_row4;
    int col = (tid - row * per_row4) << 2;
    int c   = col / sub;
    int j   = col - c * sub;
    int code = __ldg(&idx[c * rows + row]);
    float4 v = *reinterpret_cast<const float4*>(cb + ((size_t)(c * KCB + code)) * sub + j);
    uint32_t h0, h1, l0, l1;
    split4(v, h0, h1, l0, l1);
    size_t off = (size_t)row * (NCB * sub) + col;
    *reinterpret_cast<uint2*>(Whi + off) = make_uint2(h0, h1);
    *reinterpret_cast<uint2*>(Wlo + off) = make_uint2(l0, l1);
}

// ---------------------------------------------------------------------------
// Pipelined bf16 mma.sync GEMM, 3-product hi/lo accumulation.
// CTA tile 128x256, BK=64, 2-stage double buffer, 256 threads.
// 8 warps in 2(m) x 4(n); warp tile 64x64.
// Round-13: full fragment pipelining — ahi double-buffered across kk,
// alo JIT-loaded at pr==0, B double-buffered across pr AND kk boundaries,
// deferred gmem prefetch (kk==1).
// ---------------------------------------------------------------------------
#define BM 128
#define BN 256
#define BKE 64
#define TILE_A  (BM * BKE * 2)                 // 16 KB
#define TILE_BB (BN * BKE * 2)                 // 32 KB
#define STAGE_B (2 * TILE_A + 2 * TILE_BB)     // 96 KB
#define SMEM_TOT (2 * STAGE_B)                 // 192 KB

__device__ __forceinline__ void load_stage(uint32_t stage,
    const __nv_bfloat16* __restrict__ Ahi, const __nv_bfloat16* __restrict__ Alo,
    const __nv_bfloat16* __restrict__ Bhi, const __nv_bfloat16* __restrict__ Blo,
    int bm, int bn, int k0, int K, int tid)
{
    const int row = tid >> 1;            // 0..127
    const int kc0 = (tid & 1) * 4;       // 16B-chunk 0..7
    const uint32_t sw  = ((uint32_t)(row & 7)) << 4;
    const uint32_t rb  = (uint32_t)row * 128;
    const uint32_t sAh = stage;
    const uint32_t sAl = stage + TILE_A;
    const uint32_t sBh = stage + 2 * TILE_A;
    const uint32_t sBl = stage + 2 * TILE_A + TILE_BB;

    const __nv_bfloat16* pAh = Ahi + (size_t)(bm + row) * K + k0;
    const __nv_bfloat16* pAl = Alo + (size_t)(bm + row) * K + k0;
    #pragma unroll
    for (int i = 0; i < 4; i++) {
        int kc = kc0 + i;
        uint32_t d = rb + (((uint32_t)kc * 16) ^ sw);
        CP_ASYNC16(sAh + d, pAh + kc * 8);
        CP_ASYNC16(sAl + d, pAl + kc * 8);
    }
    #pragma unroll
    for (int g = 0; g < 2; g++) {
        int brow = row + g * 128;
        const __nv_bfloat16* pBh = Bhi + (size_t)(bn + brow) * K + k0;
        const __nv_bfloat16* pBl = Blo + (size_t)(bn + brow) * K + k0;
        uint32_t brb = (uint32_t)brow * 128;
        #pragma unroll
        for (int i = 0; i < 4; i++) {
            int kc = kc0 + i;
            uint32_t d = brb + (((uint32_t)kc * 16) ^ sw);
            CP_ASYNC16(sBh + d, pBh + kc * 8);
            CP_ASYNC16(sBl + d, pBl + kc * 8);
        }
    }
}

template<bool GELU, bool OUT_SPLIT>
__global__ __launch_bounds__(256, 1)
void gemm_bf3(const __nv_bfloat16* __restrict__ Ahi, const __nv_bfloat16* __restrict__ Alo,
              const __nv_bfloat16* __restrict__ Bhi, const __nv_bfloat16* __restrict__ Blo,
              const float* __restrict__ bias,
              float* __restrict__ Cf,
              __nv_bfloat16* __restrict__ Chi, __nv_bfloat16* __restrict__ Clo,
              int M, int N, int K)
{
    extern __shared__ __align__(1024) char smem[];
    const uint32_t sb = smem_u32(smem);
    const int tid  = threadIdx.x;
    const int wid  = tid >> 5;
    const int lane = tid & 31;
    const int wr   = wid & 1;          // warp m-tile (64 rows)
    const int wc   = wid >> 1;         // warp n-tile (64 cols)
    const int bm   = blockIdx.y * BM;
    const int bn   = blockIdx.x * BN;

    float acc[4][8][4];
    #pragma unroll
    for (int a = 0; a < 4; a++)
        #pragma unroll
        for (int b = 0; b < 8; b++)
            #pragma unroll
            for (int c = 0; c < 4; c++) acc[a][b][c] = 0.0f;

    // ldmatrix lane addressing
    const int amat = lane >> 3, ar = lane & 7;
    const int a_m  = wr * 64 + (amat & 1) * 8 + ar;      // + mt*16
    const uint32_t a_kh = (uint32_t)(amat >> 1) * 16;
    const uint32_t a_rb = (uint32_t)a_m * 128;
    const uint32_t a_sx = ((uint32_t)(a_m & 7)) << 4;

    const int bmat = lane >> 3, br = lane & 7;
    const int b_n  = wc * 64 + ((bmat >> 1) << 3) + br;  // + pr*16
    const uint32_t b_kh = (uint32_t)(bmat & 1) * 16;
    const uint32_t b_rb = (uint32_t)b_n * 128;
    const uint32_t b_sx = ((uint32_t)(b_n & 7)) << 4;

    const int NT = K / BKE;

    // prologue: prefetch stage 0
    load_stage(sb, Ahi, Alo, Bhi, Blo, bm, bn, 0, K, tid);
    CP_COMMIT();

    for (int it = 0; it < NT; it++) {
        CP_WAIT0();
        __syncthreads();

        const uint32_t st  = sb + (it & 1) * STAGE_B;
        const uint32_t sAh = st;
        const uint32_t sAl = st + TILE_A;
        const uint32_t sBh = st + 2 * TILE_A;
        const uint32_t sBl = st + 2 * TILE_A + TILE_BB;

        // persistent fragment buffers
        uint32_t ahi[2][4][4];     // double-buffered across kk
        uint32_t alo[4][4];        // JIT per kk
        uint32_t bh[2][4], bl[2][4];

        // preload kk0 ahi + (kk0, pr0) B
        #pragma unroll
        for (int mt = 0; mt < 4; mt++) {
            uint32_t off = a_rb + mt * 2048 + (a_kh ^ a_sx);
            LDSM_X4(ahi[0][mt][0], ahi[0][mt][1], ahi[0][mt][2], ahi[0][mt][3], sAh + off);
        }
        {
            uint32_t off0 = b_rb + (b_kh ^ b_sx);
            LDSM_X4(bh[0][0], bh[0][1], bh[0][2], bh[0][3], sBh + off0);
            LDSM_X4(bl[0][0], bl[0][1], bl[0][2], bl[0][3], sBl + off0);
        }

        #pragma unroll
        for (int kk = 0; kk < 4; kk++) {
            const int ab = kk & 1;
            const uint32_t kb = (uint32_t)kk * 32;

            // deferred gmem prefetch for next stage
            if (kk == 1) {
                int pf = it + 1;
                if (pf < NT) {
                    load_stage(sb + (pf & 1) * STAGE_B, Ahi, Alo, Bhi, Blo,
                               bm, bn, pf * BKE, K, tid);
                    CP_COMMIT();
                }
            }

            #pragma unroll
            for (int pr = 0; pr < 4; pr++) {
                const int bb = (kk * 4 + pr) & 1;
                // B prefetch: next pr, or next kk's pr0
                if (pr < 3) {
                    uint32_t offn = b_rb + (pr + 1) * 2048 + ((kb + b_kh) ^ b_sx);
                    LDSM_X4(bh[bb ^ 1][0], bh[bb ^ 1][1], bh[bb ^ 1][2], bh[bb ^ 1][3], sBh + offn);
                    LDSM_X4(bl[bb ^ 1][0], bl[bb ^ 1][1], bl[bb ^ 1][2], bl[bb ^ 1][3], sBl + offn);
                } else if (kk < 3) {
                    uint32_t offn = b_rb + (((uint32_t)(kk + 1) * 32 + b_kh) ^ b_sx);
                    LDSM_X4(bh[bb ^ 1][0], bh[bb ^ 1][1], bh[bb ^ 1][2], bh[bb ^ 1][3], sBh + offn);
                    LDSM_X4(bl[bb ^ 1][0], bl[bb ^ 1][1], bl[bb ^ 1][2], bl[bb ^ 1][3], sBl + offn);
                }
                // alo JIT load for this kk (needed first at phase3 below, ~16 MMAs later)
                if (pr == 0) {
                    #pragma unroll
                    for (int mt = 0; mt < 4; mt++) {
                        uint32_t off = a_rb + mt * 2048 + ((kb + a_kh) ^ a_sx);
                        LDSM_X4(alo[mt][0], alo[mt][1], alo[mt][2], alo[mt][3], sAl + off);
                    }
                }
                // ahi prefetch for next kk
                if (pr == 2 && kk < 3) {
                    #pragma unroll
                    for (int mt = 0; mt < 4; mt++) {
                        uint32_t off = a_rb + mt * 2048
                                     + (((uint32_t)(kk + 1) * 32 + a_kh) ^ a_sx);
                        LDSM_X4(ahi[ab ^ 1][mt][0], ahi[ab ^ 1][mt][1],
                                ahi[ab ^ 1][mt][2], ahi[ab ^ 1][mt][3], sAh + off);
                    }
                }
                // phase 1: hi*hi
                #pragma unroll
                for (int mt = 0; mt < 4; mt++) {
                    MMA_BF16(acc[mt][pr * 2 + 0], ahi[ab][mt], bh[bb][0], bh[bb][1]);
                    MMA_BF16(acc[mt][pr * 2 + 1], ahi[ab][mt], bh[bb][2], bh[bb][3]);
                }
                // phase 2: hi*lo
                #pragma unroll
                for (int mt = 0; mt < 4; mt++) {
                    MMA_BF16(acc[mt][pr * 2 + 0], ahi[ab][mt], bl[bb][0], bl[bb][1]);
                    MMA_BF16(acc[mt][pr * 2 + 1], ahi[ab][mt], bl[bb][2], bl[bb][3]);
                }
                // phase 3: lo*hi
                #pragma unroll
                for (int mt = 0; mt < 4; mt++) {
                    MMA_BF16(acc[mt][pr * 2 + 0], alo[mt], bh[bb][0], bh[bb][1]);
                    MMA_BF16(acc[mt][pr * 2 + 1], alo[mt], bh[bb][2], bh[bb][3]);
                }
            }
        }
    }

    // epilogue
    const int mrow = bm + wr * 64 + (lane >> 2);
    const int ncol = bn + wc * 64 + (lane & 3) * 2;
    #pragma unroll
    for (int mt = 0; mt < 4; mt++) {
        #pragma unroll
        for (int n8 = 0; n8 < 8; n8++) {
            const int n = ncol + n8 * 8;
            const float bs0 = __ldg(&bias[n]);
            const float bs1 = __ldg(&bias[n + 1]);
            #pragma unroll
            for (int hf = 0; hf < 2; hf++) {
                const int m = mrow + mt * 16 + hf * 8;
                float v0 = acc[mt][n8][hf * 2 + 0] + bs0;
                float v1 = acc[mt][n8][hf * 2 + 1] + bs1;
                if (GELU) {
                    v0 = 0.5f * v0 * (1.0f + erff(v0 * 0.70710678118654752440f));
                    v1 = 0.5f * v1 * (1.0f + erff(v1 * 0.70710678118654752440f));
                }
                if (OUT_SPLIT) {
                    __nv_bfloat162 h2 = __floats2bfloat162_rn(v0, v1);
                    __nv_bfloat162 l2 = __floats2bfloat162_rn(
                        v0 - __bfloat162float(h2.x), v1 - __bfloat162float(h2.y));
                    *reinterpret_cast<__nv_bfloat162*>(Chi + (size_t)m * N + n) = h2;
                    *reinterpret_cast<__nv_bfloat162*>(Clo + (size_t)m * N + n) = l2;
                } else {
                    *reinterpret_cast<float2*>(Cf + (size_t)m * N + n) = make_float2(v0, v1);
                }
            }
        }
    }
}

// ---------------------------------------------------------------------------
extern "C" void kernel_launch(void* const* d_in, const int* in_sizes, int n_in,
                              void* d_out, int out_size) {
    const float* x    = (const float*)d_in[0];
    const float* cb1  = (const float*)d_in[1];
    const int*   idx1 = (const int*)  d_in[2];
    const float* b1   = (const float*)d_in[3];
    const float* cb2  = (const float*)d_in[4];
    const int*   idx2 = (const int*)  d_in[5];
    const float* b2   = (const float*)d_in[6];
    float* out = (float*)d_out;

    __nv_bfloat16 *xhi, *xlo, *w1hi, *w1lo, *w2hi, *w2lo, *hhi, *hlo;
    cudaGetSymbolAddress((void**)&xhi,  g_xhi);
    cudaGetSymbolAddress((void**)&xlo,  g_xlo);
    cudaGetSymbolAddress((void**)&w1hi, g_w1hi);
    cudaGetSymbolAddress((void**)&w1lo, g_w1lo);
    cudaGetSymbolAddress((void**)&w2hi, g_w2hi);
    cudaGetSymbolAddress((void**)&w2lo, g_w2lo);
    cudaGetSymbolAddress((void**)&hhi,  g_hhi);
    cudaGetSymbolAddress((void**)&hlo,  g_hlo);

    cudaFuncSetAttribute(gemm_bf3<true, true>,
                         cudaFuncAttributeMaxDynamicSharedMemorySize, SMEM_TOT);
    cudaFuncSetAttribute(gemm_bf3<false, false>,
                         cudaFuncAttributeMaxDynamicSharedMemorySize, SMEM_TOT);

    {
        int n4 = (MTOK * DDIM) / 4;
        split_x_kernel<<<(n4 + 255) / 256, 256>>>(x, xhi, xlo, n4);
    }
    {
        int n4 = (HDIM * DDIM) / 4;
        dequant_split_kernel<<<(n4 + 255) / 256, 256>>>(cb1, idx1, w1hi, w1lo, HDIM, DDIM / NCB);
    }
    {
        int n4 = (DDIM * HDIM) / 4;
        dequant_split_kernel<<<(n4 + 255) / 256, 256>>>(cb2, idx2, w2hi, w2lo, DDIM, HDIM / NCB);
    }

    {
        dim3 grid(HDIM / BN, MTOK / BM);     // (16, 64)
        gemm_bf3<true, true><<<grid, 256, SMEM_TOT>>>(
            xhi, xlo, w1hi, w1lo, b1, nullptr, hhi, hlo, MTOK, HDIM, DDIM);
    }
    {
        dim3 grid(DDIM / BN, MTOK / BM);     // (4, 64)
        gemm_bf3<false, false><<<grid, 256, SMEM_TOT>>>(
            hhi, hlo, w2hi, w2lo, b2, out, nullptr, nullptr, MTOK, DDIM, HDIM);
    }
}

// round 14
// speedup vs baseline: 1.7518x; 1.3252x over previous
#include <cuda_runtime.h>
#include <cuda_fp16.h>
#include <math.h>
#include <stdint.h>

#define MTOK 8192
#define DDIM 1024
#define HDIM 4096
#define NCB  8
#define KCB  256

// fp16 operand arrays (static device scratch)
__device__ __half g_xhi [(size_t)MTOK * DDIM];
__device__ __half g_xlo [(size_t)MTOK * DDIM];
__device__ __half g_w1hi[(size_t)HDIM * DDIM];
__device__ __half g_w2hi[(size_t)DDIM * HDIM];
__device__ __half g_hhi [(size_t)MTOK * HDIM];
__device__ __half g_hlo [(size_t)MTOK * HDIM];

// ---------------------------------------------------------------------------
__device__ __forceinline__ uint32_t smem_u32(const void* p) {
    uint32_t a;
    asm("{ .reg .u64 t; cvta.to.shared.u64 t, %1; cvt.u32.u64 %0, t; }"
        : "=r"(a) : "l"(p));
    return a;
}

#define CP_ASYNC16(dst, src) \
    asm volatile("cp.async.cg.shared.global [%0], [%1], 16;" \
        :: "r"(dst), "l"(src) : "memory")
#define CP_COMMIT() asm volatile("cp.async.commit_group;" ::: "memory")
#define CP_WAIT1()  asm volatile("cp.async.wait_group 1;"  ::: "memory")

#define LDSM_X4(r0, r1, r2, r3, a) \
    asm volatile("ldmatrix.sync.aligned.m8n8.x4.shared.b16 {%0,%1,%2,%3}, [%4];" \
        : "=r"(r0), "=r"(r1), "=r"(r2), "=r"(r3) : "r"(a))

#define MMA_FP16(c, a, b0, b1) \
    asm volatile("mma.sync.aligned.m16n8k16.row.col.f32.f16.f16.f32 " \
        "{%0,%1,%2,%3}, {%4,%5,%6,%7}, {%8,%9}, {%0,%1,%2,%3};" \
        : "+f"((c)[0]), "+f"((c)[1]), "+f"((c)[2]), "+f"((c)[3]) \
        : "r"((a)[0]), "r"((a)[1]), "r"((a)[2]), "r"((a)[3]), "r"(b0), "r"(b1))

// ---------------------------------------------------------------------------
// Pre-pass kernels (fp16 hi/lo)
// ---------------------------------------------------------------------------
__device__ __forceinline__ void splitf16_4(float4 v,
                                           uint32_t& hi0, uint32_t& hi1,
                                           uint32_t& lo0, uint32_t& lo1) {
    __half h0 = __float2half_rn(v.x), h1 = __float2half_rn(v.y);
    __half h2 = __float2half_rn(v.z), h3 = __float2half_rn(v.w);
    __half l0 = __float2half_rn(v.x - __half2float(h0));
    __half l1 = __float2half_rn(v.y - __half2float(h1));
    __half l2 = __float2half_rn(v.z - __half2float(h2));
    __half l3 = __float2half_rn(v.w - __half2float(h3));
    __half2 H01 = __halves2half2(h0, h1), H23 = __halves2half2(h2, h3);
    __half2 L01 = __halves2half2(l0, l1), L23 = __halves2half2(l2, l3);
    memcpy(&hi0, &H01, 4); memcpy(&hi1, &H23, 4);
    memcpy(&lo0, &L01, 4); memcpy(&lo1, &L23, 4);
}

__global__ void split_x_kernel(const float* __restrict__ x,
                               __half* __restrict__ xhi,
                               __half* __restrict__ xlo, int n4) {
    int i = blockIdx.x * blockDim.x + threadIdx.x;
    if (i >= n4) return;
    float4 v = reinterpret_cast<const float4*>(x)[i];
    uint32_t h0, h1, l0, l1;
    splitf16_4(v, h0, h1, l0, l1);
    reinterpret_cast<uint2*>(xhi)[i] = make_uint2(h0, h1);
    reinterpret_cast<uint2*>(xlo)[i] = make_uint2(l0, l1);
}

// Dequant weight and round to fp16 (hi only — B side uses single product)
__global__ void dequant_f16_kernel(const float* __restrict__ cb,
                                   const int*   __restrict__ idx,
                                   __half* __restrict__ Whi,
                                   int rows, int sub) {
    const int per_row4 = (NCB * sub) >> 2;
    int tid = blockIdx.x * blockDim.x + threadIdx.x;
    if (tid >= rows * per_row4) return;
    int row = tid / per_row4;
    int col = (tid - row * per_row4) << 2;
    int c   = col / sub;
    int j   = col - c * sub;
    int code = __ldg(&idx[c * rows + row]);
    float4 v = *reinterpret_cast<const float4*>(cb + ((size_t)(c * KCB + code)) * sub + j);
    __half2 H01 = __floats2half2_rn(v.x, v.y);
    __half2 H23 = __floats2half2_rn(v.z, v.w);
    uint32_t h0, h1;
    memcpy(&h0, &H01, 4); memcpy(&h1, &H23, 4);
    *reinterpret_cast<uint2*>(Whi + (size_t)row * (NCB * sub) + col) = make_uint2(h0, h1);
}

// ---------------------------------------------------------------------------
// Pipelined fp16 mma.sync GEMM, 2-product (Ahi+Alo)*Bhi accumulation.
// C[m,n] = sum_k A[m,k]*B[n,k] (+bias, opt GELU).
// CTA tile 128x256, BK=64, 3-stage cp.async pipeline, 256 threads.
// 8 warps in 2(m) x 4(n); warp tile 64x64.
// ---------------------------------------------------------------------------
#define BM 128
#define BN 256
#define BKE 64
#define TILE_A  (BM * BKE * 2)                 // 16 KB
#define TILE_BB (BN * BKE * 2)                 // 32 KB
#define STAGE_B (2 * TILE_A + TILE_BB)         // 64 KB: Ahi, Alo, Bhi
#define NSTAGE  3
#define SMEM_TOT (NSTAGE * STAGE_B)            // 192 KB

__device__ __forceinline__ void load_stage(uint32_t stage,
    const __half* __restrict__ Ahi, const __half* __restrict__ Alo,
    const __half* __restrict__ Bhi,
    int bm, int bn, int k0, int K, int tid)
{
    const int row = tid >> 1;            // 0..127
    const int kc0 = (tid & 1) * 4;       // 16B-chunk 0..7
    const uint32_t sw  = ((uint32_t)(row & 7)) << 4;
    const uint32_t rb  = (uint32_t)row * 128;
    const uint32_t sAh = stage;
    const uint32_t sAl = stage + TILE_A;
    const uint32_t sBh = stage + 2 * TILE_A;

    const __half* pAh = Ahi + (size_t)(bm + row) * K + k0;
    const __half* pAl = Alo + (size_t)(bm + row) * K + k0;
    #pragma unroll
    for (int i = 0; i < 4; i++) {
        int kc = kc0 + i;
        uint32_t d = rb + (((uint32_t)kc * 16) ^ sw);
        CP_ASYNC16(sAh + d, pAh + kc * 8);
        CP_ASYNC16(sAl + d, pAl + kc * 8);
    }
    #pragma unroll
    for (int g = 0; g < 2; g++) {
        int brow = row + g * 128;
        const __half* pBh = Bhi + (size_t)(bn + brow) * K + k0;
        uint32_t brb = (uint32_t)brow * 128;
        #pragma unroll
        for (int i = 0; i < 4; i++) {
            int kc = kc0 + i;
            uint32_t d = brb + (((uint32_t)kc * 16) ^ sw);
            CP_ASYNC16(sBh + d, pBh + kc * 8);
        }
    }
}

template<bool GELU, bool OUT_SPLIT>
__global__ __launch_bounds__(256, 1)
void gemm_f16(const __half* __restrict__ Ahi, const __half* __restrict__ Alo,
              const __half* __restrict__ Bhi,
              const float* __restrict__ bias,
              float* __restrict__ Cf,
              __half* __restrict__ Chi, __half* __restrict__ Clo,
              int M, int N, int K)
{
    extern __shared__ __align__(1024) char smem[];
    const uint32_t sb = smem_u32(smem);
    const int tid  = threadIdx.x;
    const int wid  = tid >> 5;
    const int lane = tid & 31;
    const int wr   = wid & 1;          // warp m-tile (64 rows)
    const int wc   = wid >> 1;         // warp n-tile (64 cols)
    const int bm   = blockIdx.y * BM;
    const int bn   = blockIdx.x * BN;

    float acc[4][8][4];
    #pragma unroll
    for (int a = 0; a < 4; a++)
        #pragma unroll
        for (int b = 0; b < 8; b++)
            #pragma unroll
            for (int c = 0; c < 4; c++) acc[a][b][c] = 0.0f;

    // ldmatrix lane addressing
    const int amat = lane >> 3, ar = lane & 7;
    const int a_m  = wr * 64 + (amat & 1) * 8 + ar;      // + mt*16
    const uint32_t a_kh = (uint32_t)(amat >> 1) * 16;
    const uint32_t a_rb = (uint32_t)a_m * 128;
    const uint32_t a_sx = ((uint32_t)(a_m & 7)) << 4;

    const int bmat = lane >> 3, br = lane & 7;
    const int b_n  = wc * 64 + ((bmat >> 1) << 3) + br;  // + pr*16
    const uint32_t b_kh = (uint32_t)(bmat & 1) * 16;
    const uint32_t b_rb = (uint32_t)b_n * 128;
    const uint32_t b_sx = ((uint32_t)(b_n & 7)) << 4;

    const int NT = K / BKE;

    // prologue: prefetch 2 stages
    load_stage(sb, Ahi, Alo, Bhi, bm, bn, 0, K, tid);
    CP_COMMIT();
    load_stage(sb + STAGE_B, Ahi, Alo, Bhi, bm, bn, BKE, K, tid);
    CP_COMMIT();

    for (int it = 0; it < NT; it++) {
        CP_WAIT1();
        __syncthreads();

        const uint32_t st  = sb + (it % NSTAGE) * STAGE_B;
        const uint32_t sAh = st;
        const uint32_t sAl = st + TILE_A;
        const uint32_t sBh = st + 2 * TILE_A;

        #pragma unroll
        for (int kk = 0; kk < 4; kk++) {
            // deferred gmem prefetch for stage it+2
            if (kk == 1) {
                int pf = it + 2;
                if (pf < NT)
                    load_stage(sb + (pf % NSTAGE) * STAGE_B, Ahi, Alo, Bhi,
                               bm, bn, pf * BKE, K, tid);
                CP_COMMIT();   // always commit to keep wait_group math exact
            }

            const uint32_t kb = (uint32_t)kk * 32;
            uint32_t ahi[4][4], alo[4][4];
            #pragma unroll
            for (int mt = 0; mt < 4; mt++) {
                uint32_t off = a_rb + mt * 2048 + ((kb + a_kh) ^ a_sx);
                LDSM_X4(ahi[mt][0], ahi[mt][1], ahi[mt][2], ahi[mt][3], sAh + off);
                LDSM_X4(alo[mt][0], alo[mt][1], alo[mt][2], alo[mt][3], sAl + off);
            }

            // B fragment double buffer across pr
            uint32_t bh[2][4];
            {
                uint32_t off0 = b_rb + ((kb + b_kh) ^ b_sx);
                LDSM_X4(bh[0][0], bh[0][1], bh[0][2], bh[0][3], sBh + off0);
            }
            #pragma unroll
            for (int pr = 0; pr < 4; pr++) {
                const int cur = pr & 1;
                if (pr < 3) {
                    uint32_t offn = b_rb + (pr + 1) * 2048 + ((kb + b_kh) ^ b_sx);
                    LDSM_X4(bh[cur ^ 1][0], bh[cur ^ 1][1], bh[cur ^ 1][2], bh[cur ^ 1][3],
                            sBh + offn);
                }
                // phase 1: hi * B
                #pragma unroll
                for (int mt = 0; mt < 4; mt++) {
                    MMA_FP16(acc[mt][pr * 2 + 0], ahi[mt], bh[cur][0], bh[cur][1]);
                    MMA_FP16(acc[mt][pr * 2 + 1], ahi[mt], bh[cur][2], bh[cur][3]);
                }
                // phase 2: lo * B
                #pragma unroll
                for (int mt = 0; mt < 4; mt++) {
                    MMA_FP16(acc[mt][pr * 2 + 0], alo[mt], bh[cur][0], bh[cur][1]);
                    MMA_FP16(acc[mt][pr * 2 + 1], alo[mt], bh[cur][2], bh[cur][3]);
                }
            }
        }
    }

    // epilogue
    const int mrow = bm + wr * 64 + (lane >> 2);
    const int ncol = bn + wc * 64 + (lane & 3) * 2;
    #pragma unroll
    for (int mt = 0; mt < 4; mt++) {
        #pragma unroll
        for (int n8 = 0; n8 < 8; n8++) {
            const int n = ncol + n8 * 8;
            const float bs0 = __ldg(&bias[n]);
            const float bs1 = __ldg(&bias[n + 1]);
            #pragma unroll
            for (int hf = 0; hf < 2; hf++) {
                const int m = mrow + mt * 16 + hf * 8;
                float v0 = acc[mt][n8][hf * 2 + 0] + bs0;
                float v1 = acc[mt][n8][hf * 2 + 1] + bs1;
                if (GELU) {
                    v0 = 0.5f * v0 * (1.0f + erff(v0 * 0.70710678118654752440f));
                    v1 = 0.5f * v1 * (1.0f + erff(v1 * 0.70710678118654752440f));
                }
                if (OUT_SPLIT) {
                    __half h0 = __float2half_rn(v0);
                    __half h1 = __float2half_rn(v1);
                    __half l0 = __float2half_rn(v0 - __half2float(h0));
                    __half l1 = __float2half_rn(v1 - __half2float(h1));
                    *reinterpret_cast<__half2*>(Chi + (size_t)m * N + n) = __halves2half2(h0, h1);
                    *reinterpret_cast<__half2*>(Clo + (size_t)m * N + n) = __halves2half2(l0, l1);
                } else {
                    *reinterpret_cast<float2*>(Cf + (size_t)m * N + n) = make_float2(v0, v1);
                }
            }
        }
    }
}

// ---------------------------------------------------------------------------
extern "C" void kernel_launch(void* const* d_in, const int* in_sizes, int n_in,
                              void* d_out, int out_size) {
    const float* x    = (const float*)d_in[0];
    const float* cb1  = (const float*)d_in[1];
    const int*   idx1 = (const int*)  d_in[2];
    const float* b1   = (const float*)d_in[3];
    const float* cb2  = (const float*)d_in[4];
    const int*   idx2 = (const int*)  d_in[5];
    const float* b2   = (const float*)d_in[6];
    float* out = (float*)d_out;

    __half *xhi, *xlo, *w1hi, *w2hi, *hhi, *hlo;
    cudaGetSymbolAddress((void**)&xhi,  g_xhi);
    cudaGetSymbolAddress((void**)&xlo,  g_xlo);
    cudaGetSymbolAddress((void**)&w1hi, g_w1hi);
    cudaGetSymbolAddress((void**)&w2hi, g_w2hi);
    cudaGetSymbolAddress((void**)&hhi,  g_hhi);
    cudaGetSymbolAddress((void**)&hlo,  g_hlo);

    cudaFuncSetAttribute(gemm_f16<true, true>,
                         cudaFuncAttributeMaxDynamicSharedMemorySize, SMEM_TOT);
    cudaFuncSetAttribute(gemm_f16<false, false>,
                         cudaFuncAttributeMaxDynamicSharedMemorySize, SMEM_TOT);

    {
        int n4 = (MTOK * DDIM) / 4;
        split_x_kernel<<<(n4 + 255) / 256, 256>>>(x, xhi, xlo, n4);
    }
    {
        int n4 = HDIM * (DDIM / 4);
        dequant_f16_kernel<<<(n4 + 255) / 256, 256>>>(cb1, idx1, w1hi, HDIM, DDIM / NCB);
    }
    {
        int n4 = DDIM * (HDIM / 4);
        dequant_f16_kernel<<<(n4 + 255) / 256, 256>>>(cb2, idx2, w2hi, DDIM, HDIM / NCB);
    }

    // GEMM1: h = gelu(x @ W1^T + b1), written as fp16 hi/lo
    {
        dim3 grid(HDIM / BN, MTOK / BM);     // (16, 64)
        gemm_f16<true, true><<<grid, 256, SMEM_TOT>>>(
            xhi, xlo, w1hi, b1, nullptr, hhi, hlo, MTOK, HDIM, DDIM);
    }
    // GEMM2: out = h @ W2^T + b2 (fp32)
    {
        dim3 grid(DDIM / BN, MTOK / BM);     // (4, 64)
        gemm_f16<false, false><<<grid, 256, SMEM_TOT>>>(
            hhi, hlo, w2hi, b2, out, nullptr, nullptr, MTOK, DDIM, HDIM);
    }
}

// round 16
// speedup vs baseline: 1.9217x; 1.0970x over previous
#include <cuda_runtime.h>
#include <cuda_fp16.h>
#include <math.h>
#include <stdint.h>

#define MTOK 8192
#define DDIM 1024
#define HDIM 4096
#define NCB  8
#define KCB  256

// fp16 operand arrays (static device scratch)
__device__ __half g_xhi [(size_t)MTOK * DDIM];
__device__ __half g_xlo [(size_t)MTOK * DDIM];
__device__ __half g_w1hi[(size_t)HDIM * DDIM];
__device__ __half g_w2hi[(size_t)DDIM * HDIM];
__device__ __half g_hhi [(size_t)MTOK * HDIM];
__device__ __half g_hlo [(size_t)MTOK * HDIM];

// ---------------------------------------------------------------------------
__device__ __forceinline__ uint32_t smem_u32(const void* p) {
    uint32_t a;
    asm("{ .reg .u64 t; cvta.to.shared.u64 t, %1; cvt.u32.u64 %0, t; }"
        : "=r"(a) : "l"(p));
    return a;
}

#define CP_ASYNC16(dst, src) \
    asm volatile("cp.async.cg.shared.global [%0], [%1], 16;" \
        :: "r"(dst), "l"(src) : "memory")
#define CP_COMMIT() asm volatile("cp.async.commit_group;" ::: "memory")
#define CP_WAIT1()  asm volatile("cp.async.wait_group 1;"  ::: "memory")

#define LDSM_X4(r0, r1, r2, r3, a) \
    asm volatile("ldmatrix.sync.aligned.m8n8.x4.shared.b16 {%0,%1,%2,%3}, [%4];" \
        : "=r"(r0), "=r"(r1), "=r"(r2), "=r"(r3) : "r"(a))

#define MMA_FP16(c, a, b0, b1) \
    asm volatile("mma.sync.aligned.m16n8k16.row.col.f32.f16.f16.f32 " \
        "{%0,%1,%2,%3}, {%4,%5,%6,%7}, {%8,%9}, {%0,%1,%2,%3};" \
        : "+f"((c)[0]), "+f"((c)[1]), "+f"((c)[2]), "+f"((c)[3]) \
        : "r"((a)[0]), "r"((a)[1]), "r"((a)[2]), "r"((a)[3]), "r"(b0), "r"(b1))

// ---------------------------------------------------------------------------
// Pre-pass kernels (fp16 hi/lo)
// ---------------------------------------------------------------------------
__device__ __forceinline__ void splitf16_4(float4 v,
                                           uint32_t& hi0, uint32_t& hi1,
                                           uint32_t& lo0, uint32_t& lo1) {
    __half h0 = __float2half_rn(v.x), h1 = __float2half_rn(v.y);
    __half h2 = __float2half_rn(v.z), h3 = __float2half_rn(v.w);
    __half l0 = __float2half_rn(v.x - __half2float(h0));
    __half l1 = __float2half_rn(v.y - __half2float(h1));
    __half l2 = __float2half_rn(v.z - __half2float(h2));
    __half l3 = __float2half_rn(v.w - __half2float(h3));
    __half2 H01 = __halves2half2(h0, h1), H23 = __halves2half2(h2, h3);
    __half2 L01 = __halves2half2(l0, l1), L23 = __halves2half2(l2, l3);
    memcpy(&hi0, &H01, 4); memcpy(&hi1, &H23, 4);
    memcpy(&lo0, &L01, 4); memcpy(&lo1, &L23, 4);
}

__global__ void split_x_kernel(const float* __restrict__ x,
                               __half* __restrict__ xhi,
                               __half* __restrict__ xlo, int n4) {
    int i = blockIdx.x * blockDim.x + threadIdx.x;
    if (i >= n4) return;
    float4 v = reinterpret_cast<const float4*>(x)[i];
    uint32_t h0, h1, l0, l1;
    splitf16_4(v, h0, h1, l0, l1);
    reinterpret_cast<uint2*>(xhi)[i] = make_uint2(h0, h1);
    reinterpret_cast<uint2*>(xlo)[i] = make_uint2(l0, l1);
}

__global__ void dequant_f16_kernel(const float* __restrict__ cb,
                                   const int*   __restrict__ idx,
                                   __half* __restrict__ Whi,
                                   int rows, int sub) {
    const int per_row4 = (NCB * sub) >> 2;
    int tid = blockIdx.x * blockDim.x + threadIdx.x;
    if (tid >= rows * per_row4) return;
    int row = tid / per_row4;
    int col = (tid - row * per_row4) << 2;
    int c   = col / sub;
    int j   = col - c * sub;
    int code = __ldg(&idx[c * rows + row]);
    float4 v = *reinterpret_cast<const float4*>(cb + ((size_t)(c * KCB + code)) * sub + j);
    __half2 H01 = __floats2half2_rn(v.x, v.y);
    __half2 H23 = __floats2half2_rn(v.z, v.w);
    uint32_t h0, h1;
    memcpy(&h0, &H01, 4); memcpy(&h1, &H23, 4);
    *reinterpret_cast<uint2*>(Whi + (size_t)row * (NCB * sub) + col) = make_uint2(h0, h1);
}

// ---------------------------------------------------------------------------
// Pipelined fp16 mma.sync GEMM, 2-product (Ahi+Alo)*Bhi accumulation.
// CTA tile 128x256, BK=64, 3-stage pipeline, 512 threads (16 warps, 4m x 4n).
// Warp tile 32x64 — 4 warps per SMSP for latency hiding.
// ---------------------------------------------------------------------------
#define BM 128
#define BN 256
#define BKE 64
#define TILE_A  (BM * BKE * 2)                 // 16 KB
#define TILE_BB (BN * BKE * 2)                 // 32 KB
#define STAGE_B (2 * TILE_A + TILE_BB)         // 64 KB: Ahi, Alo, Bhi
#define NSTAGE  3
#define SMEM_TOT (NSTAGE * STAGE_B)            // 192 KB

__device__ __forceinline__ void load_stage(uint32_t stage,
    const __half* __restrict__ Ahi, const __half* __restrict__ Alo,
    const __half* __restrict__ Bhi,
    int bm, int bn, int k0, int K, int tid)
{
    // A tiles: 128 rows x 8 chunks; 512 thr -> 2 chunks/thread per tile
    {
        const int row = tid >> 2;            // 0..127
        const int kc0 = (tid & 3) * 2;       // 0,2,4,6
        const uint32_t sw = ((uint32_t)(row & 7)) << 4;
        const uint32_t rb = (uint32_t)row * 128;
        const __half* pAh = Ahi + (size_t)(bm + row) * K + k0;
        const __half* pAl = Alo + (size_t)(bm + row) * K + k0;
        #pragma unroll
        for (int i = 0; i < 2; i++) {
            int kc = kc0 + i;
            uint32_t d = rb + (((uint32_t)kc * 16) ^ sw);
            CP_ASYNC16(stage + d, pAh + kc * 8);
            CP_ASYNC16(stage + TILE_A + d, pAl + kc * 8);
        }
    }
    // B tile: 256 rows x 8 chunks; 512 thr -> 4 chunks/thread
    {
        const int brow = tid >> 1;           // 0..255
        const int kc0  = (tid & 1) * 4;      // 0,4
        const uint32_t sw  = ((uint32_t)(brow & 7)) << 4;
        const uint32_t brb = (uint32_t)brow * 128;
        const __half* pBh = Bhi + (size_t)(bn + brow) * K + k0;
        #pragma unroll
        for (int i = 0; i < 4; i++) {
            int kc = kc0 + i;
            uint32_t d = brb + (((uint32_t)kc * 16) ^ sw);
            CP_ASYNC16(stage + 2 * TILE_A + d, pBh + kc * 8);
        }
    }
}

template<bool GELU, bool OUT_SPLIT>
__global__ __launch_bounds__(512, 1)
void gemm_f16(const __half* __restrict__ Ahi, const __half* __restrict__ Alo,
              const __half* __restrict__ Bhi,
              const float* __restrict__ bias,
              float* __restrict__ Cf,
              __half* __restrict__ Chi, __half* __restrict__ Clo,
              int M, int N, int K)
{
    extern __shared__ __align__(1024) char smem[];
    const uint32_t sb = smem_u32(smem);
    const int tid  = threadIdx.x;
    const int wid  = tid >> 5;
    const int lane = tid & 31;
    const int wr   = wid & 3;          // warp m-tile (32 rows)
    const int wc   = wid >> 2;         // warp n-tile (64 cols)
    const int bm   = blockIdx.y * BM;
    const int bn   = blockIdx.x * BN;

    float acc[2][8][4];                // [mt][pr*2+hf][4]
    #pragma unroll
    for (int a = 0; a < 2; a++)
        #pragma unroll
        for (int b = 0; b < 8; b++)
            #pragma unroll
            for (int c = 0; c < 4; c++) acc[a][b][c] = 0.0f;

    // ldmatrix lane addressing
    const int amat = lane >> 3, ar = lane & 7;
    const int a_m  = wr * 32 + (amat & 1) * 8 + ar;      // + mt*16
    const uint32_t a_kh = (uint32_t)(amat >> 1) * 16;
    const uint32_t a_rb = (uint32_t)a_m * 128;
    const uint32_t a_sx = ((uint32_t)(a_m & 7)) << 4;

    const int bmat = lane >> 3, br = lane & 7;
    const int b_n  = wc * 64 + ((bmat >> 1) << 3) + br;  // + pr*16
    const uint32_t b_kh = (uint32_t)(bmat & 1) * 16;
    const uint32_t b_rb = (uint32_t)b_n * 128;
    const uint32_t b_sx = ((uint32_t)(b_n & 7)) << 4;

    const int NT = K / BKE;

    // prologue: prefetch 2 stages
    load_stage(sb, Ahi, Alo, Bhi, bm, bn, 0, K, tid);
    CP_COMMIT();
    load_stage(sb + STAGE_B, Ahi, Alo, Bhi, bm, bn, BKE, K, tid);
    CP_COMMIT();

    for (int it = 0; it < NT; it++) {
        CP_WAIT1();
        __syncthreads();

        const uint32_t st  = sb + (it % NSTAGE) * STAGE_B;
        const uint32_t sAh = st;
        const uint32_t sAl = st + TILE_A;
        const uint32_t sBh = st + 2 * TILE_A;

        #pragma unroll
        for (int kk = 0; kk < 4; kk++) {
            // deferred gmem prefetch for stage it+2
            if (kk == 1) {
                int pf = it + 2;
                if (pf < NT)
                    load_stage(sb + (pf % NSTAGE) * STAGE_B, Ahi, Alo, Bhi,
                               bm, bn, pf * BKE, K, tid);
                CP_COMMIT();   // always commit to keep wait_group math exact
            }

            const uint32_t kb = (uint32_t)kk * 32;
            uint32_t ahi[2][4], alo[2][4];
            #pragma unroll
            for (int mt = 0; mt < 2; mt++) {
                uint32_t off = a_rb + mt * 2048 + ((kb + a_kh) ^ a_sx);
                LDSM_X4(ahi[mt][0], ahi[mt][1], ahi[mt][2], ahi[mt][3], sAh + off);
                LDSM_X4(alo[mt][0], alo[mt][1], alo[mt][2], alo[mt][3], sAl + off);
            }

            // B fragment double buffer across pr
            uint32_t bh[2][4];
            {
                uint32_t off0 = b_rb + ((kb + b_kh) ^ b_sx);
                LDSM_X4(bh[0][0], bh[0][1], bh[0][2], bh[0][3], sBh + off0);
            }
            #pragma unroll
            for (int pr = 0; pr < 4; pr++) {
                const int cur = pr & 1;
                if (pr < 3) {
                    uint32_t offn = b_rb + (pr + 1) * 2048 + ((kb + b_kh) ^ b_sx);
                    LDSM_X4(bh[cur ^ 1][0], bh[cur ^ 1][1], bh[cur ^ 1][2], bh[cur ^ 1][3],
                            sBh + offn);
                }
                // phase 1: hi * B
                #pragma unroll
                for (int mt = 0; mt < 2; mt++) {
                    MMA_FP16(acc[mt][pr * 2 + 0], ahi[mt], bh[cur][0], bh[cur][1]);
                    MMA_FP16(acc[mt][pr * 2 + 1], ahi[mt], bh[cur][2], bh[cur][3]);
                }
                // phase 2: lo * B
                #pragma unroll
                for (int mt = 0; mt < 2; mt++) {
                    MMA_FP16(acc[mt][pr * 2 + 0], alo[mt], bh[cur][0], bh[cur][1]);
                    MMA_FP16(acc[mt][pr * 2 + 1], alo[mt], bh[cur][2], bh[cur][3]);
                }
            }
        }
    }

    // epilogue
    const int mrow = bm + wr * 32 + (lane >> 2);
    const int ncol = bn + wc * 64 + (lane & 3) * 2;
    #pragma unroll
    for (int mt = 0; mt < 2; mt++) {
        #pragma unroll
        for (int n8 = 0; n8 < 8; n8++) {
            const int n = ncol + n8 * 8;
            const float bs0 = __ldg(&bias[n]);
            const float bs1 = __ldg(&bias[n + 1]);
            #pragma unroll
            for (int hf = 0; hf < 2; hf++) {
                const int m = mrow + mt * 16 + hf * 8;
                float v0 = acc[mt][n8][hf * 2 + 0] + bs0;
                float v1 = acc[mt][n8][hf * 2 + 1] + bs1;
                if (GELU) {
                    v0 = 0.5f * v0 * (1.0f + erff(v0 * 0.70710678118654752440f));
                    v1 = 0.5f * v1 * (1.0f + erff(v1 * 0.70710678118654752440f));
                }
                if (OUT_SPLIT) {
                    __half h0 = __float2half_rn(v0);
                    __half h1 = __float2half_rn(v1);
                    __half l0 = __float2half_rn(v0 - __half2float(h0));
                    __half l1 = __float2half_rn(v1 - __half2float(h1));
                    *reinterpret_cast<__half2*>(Chi + (size_t)m * N + n) = __halves2half2(h0, h1);
                    *reinterpret_cast<__half2*>(Clo + (size_t)m * N + n) = __halves2half2(l0, l1);
                } else {
                    *reinterpret_cast<float2*>(Cf + (size_t)m * N + n) = make_float2(v0, v1);
                }
            }
        }
    }
}

// ---------------------------------------------------------------------------
extern "C" void kernel_launch(void* const* d_in, const int* in_sizes, int n_in,
                              void* d_out, int out_size) {
    const float* x    = (const float*)d_in[0];
    const float* cb1  = (const float*)d_in[1];
    const int*   idx1 = (const int*)  d_in[2];
    const float* b1   = (const float*)d_in[3];
    const float* cb2  = (const float*)d_in[4];
    const int*   idx2 = (const int*)  d_in[5];
    const float* b2   = (const float*)d_in[6];
    float* out = (float*)d_out;

    __half *xhi, *xlo, *w1hi, *w2hi, *hhi, *hlo;
    cudaGetSymbolAddress((void**)&xhi,  g_xhi);
    cudaGetSymbolAddress((void**)&xlo,  g_xlo);
    cudaGetSymbolAddress((void**)&w1hi, g_w1hi);
    cudaGetSymbolAddress((void**)&w2hi, g_w2hi);
    cudaGetSymbolAddress((void**)&hhi,  g_hhi);
    cudaGetSymbolAddress((void**)&hlo,  g_hlo);

    cudaFuncSetAttribute(gemm_f16<true, true>,
                         cudaFuncAttributeMaxDynamicSharedMemorySize, SMEM_TOT);
    cudaFuncSetAttribute(gemm_f16<false, false>,
                         cudaFuncAttributeMaxDynamicSharedMemorySize, SMEM_TOT);

    {
        int n4 = (MTOK * DDIM) / 4;
        split_x_kernel<<<(n4 + 255) / 256, 256>>>(x, xhi, xlo, n4);
    }
    {
        int n4 = HDIM * (DDIM / 4);
        dequant_f16_kernel<<<(n4 + 255) / 256, 256>>>(cb1, idx1, w1hi, HDIM, DDIM / NCB);
    }
    {
        int n4 = DDIM * (HDIM / 4);
        dequant_f16_kernel<<<(n4 + 255) / 256, 256>>>(cb2, idx2, w2hi, DDIM, HDIM / NCB);
    }

    // GEMM1: h = gelu(x @ W1^T + b1), written as fp16 hi/lo
    {
        dim3 grid(HDIM / BN, MTOK / BM);     // (16, 64)
        gemm_f16<true, true><<<grid, 512, SMEM_TOT>>>(
            xhi, xlo, w1hi, b1, nullptr, hhi, hlo, MTOK, HDIM, DDIM);
    }
    // GEMM2: out = h @ W2^T + b2 (fp32)
    {
        dim3 grid(DDIM / BN, MTOK / BM);     // (4, 64)
        gemm_f16<false, false><<<grid, 512, SMEM_TOT>>>(
            hhi, hlo, w2hi, b2, out, nullptr, nullptr, MTOK, DDIM, HDIM);
    }
}

// round 17
// speedup vs baseline: 1.9716x; 1.0260x over previous
#include <cuda_runtime.h>
#include <cuda_fp16.h>
#include <math.h>
#include <stdint.h>

#define MTOK 8192
#define DDIM 1024
#define HDIM 4096
#define NCB  8
#define KCB  256

// fp16 operand arrays (static device scratch)
__device__ __half g_xhi [(size_t)MTOK * DDIM];
__device__ __half g_xlo [(size_t)MTOK * DDIM];
__device__ __half g_w1hi[(size_t)HDIM * DDIM];
__device__ __half g_w2hi[(size_t)DDIM * HDIM];
__device__ __half g_hhi [(size_t)MTOK * HDIM];
__device__ __half g_hlo [(size_t)MTOK * HDIM];

// ---------------------------------------------------------------------------
__device__ __forceinline__ uint32_t smem_u32(const void* p) {
    uint32_t a;
    asm("{ .reg .u64 t; cvta.to.shared.u64 t, %1; cvt.u32.u64 %0, t; }"
        : "=r"(a) : "l"(p));
    return a;
}

#define CP_ASYNC16(dst, src) \
    asm volatile("cp.async.cg.shared.global [%0], [%1], 16;" \
        :: "r"(dst), "l"(src) : "memory")
#define CP_COMMIT() asm volatile("cp.async.commit_group;" ::: "memory")
#define CP_WAIT1()  asm volatile("cp.async.wait_group 1;"  ::: "memory")

#define LDSM_X4(r0, r1, r2, r3, a) \
    asm volatile("ldmatrix.sync.aligned.m8n8.x4.shared.b16 {%0,%1,%2,%3}, [%4];" \
        : "=r"(r0), "=r"(r1), "=r"(r2), "=r"(r3) : "r"(a))

#define MMA_FP16(c, a, b0, b1) \
    asm volatile("mma.sync.aligned.m16n8k16.row.col.f32.f16.f16.f32 " \
        "{%0,%1,%2,%3}, {%4,%5,%6,%7}, {%8,%9}, {%0,%1,%2,%3};" \
        : "+f"((c)[0]), "+f"((c)[1]), "+f"((c)[2]), "+f"((c)[3]) \
        : "r"((a)[0]), "r"((a)[1]), "r"((a)[2]), "r"((a)[3]), "r"(b0), "r"(b1))

// ---------------------------------------------------------------------------
// Pre-pass kernels (fp16 hi/lo)
// ---------------------------------------------------------------------------
__device__ __forceinline__ void splitf16_4(float4 v,
                                           uint32_t& hi0, uint32_t& hi1,
                                           uint32_t& lo0, uint32_t& lo1) {
    __half h0 = __float2half_rn(v.x), h1 = __float2half_rn(v.y);
    __half h2 = __float2half_rn(v.z), h3 = __float2half_rn(v.w);
    __half l0 = __float2half_rn(v.x - __half2float(h0));
    __half l1 = __float2half_rn(v.y - __half2float(h1));
    __half l2 = __float2half_rn(v.z - __half2float(h2));
    __half l3 = __float2half_rn(v.w - __half2float(h3));
    __half2 H01 = __halves2half2(h0, h1), H23 = __halves2half2(h2, h3);
    __half2 L01 = __halves2half2(l0, l1), L23 = __halves2half2(l2, l3);
    memcpy(&hi0, &H01, 4); memcpy(&hi1, &H23, 4);
    memcpy(&lo0, &L01, 4); memcpy(&lo1, &L23, 4);
}

__global__ void split_x_kernel(const float* __restrict__ x,
                               __half* __restrict__ xhi,
                               __half* __restrict__ xlo, int n4) {
    int i = blockIdx.x * blockDim.x + threadIdx.x;
    if (i >= n4) return;
    float4 v = reinterpret_cast<const float4*>(x)[i];
    uint32_t h0, h1, l0, l1;
    splitf16_4(v, h0, h1, l0, l1);
    reinterpret_cast<uint2*>(xhi)[i] = make_uint2(h0, h1);
    reinterpret_cast<uint2*>(xlo)[i] = make_uint2(l0, l1);
}

__global__ void dequant_f16_kernel(const float* __restrict__ cb,
                                   const int*   __restrict__ idx,
                                   __half* __restrict__ Whi,
                                   int rows, int sub) {
    const int per_row4 = (NCB * sub) >> 2;
    int tid = blockIdx.x * blockDim.x + threadIdx.x;
    if (tid >= rows * per_row4) return;
    int row = tid / per_row4;
    int col = (tid - row * per_row4) << 2;
    int c   = col / sub;
    int j   = col - c * sub;
    int code = __ldg(&idx[c * rows + row]);
    float4 v = *reinterpret_cast<const float4*>(cb + ((size_t)(c * KCB + code)) * sub + j);
    __half2 H01 = __floats2half2_rn(v.x, v.y);
    __half2 H23 = __floats2half2_rn(v.z, v.w);
    uint32_t h0, h1;
    memcpy(&h0, &H01, 4); memcpy(&h1, &H23, 4);
    *reinterpret_cast<uint2*>(Whi + (size_t)row * (NCB * sub) + col) = make_uint2(h0, h1);
}

// ---------------------------------------------------------------------------
// Pipelined fp16 mma.sync GEMM, 2-product (Ahi+Alo)*Bhi accumulation.
// CTA tile 128x256, BK=64, 3-stage pipeline, 1024 threads (32 warps, 8m x 4n).
// Warp tile 16x64 — 8 warps per SMSP for deep latency hiding; 48 live
// fragment/acc registers per thread fits the 64-reg cap at 1024 threads.
// ---------------------------------------------------------------------------
#define BM 128
#define BN 256
#define BKE 64
#define TILE_A  (BM * BKE * 2)                 // 16 KB
#define TILE_BB (BN * BKE * 2)                 // 32 KB
#define STAGE_B (2 * TILE_A + TILE_BB)         // 64 KB: Ahi, Alo, Bhi
#define NSTAGE  3
#define SMEM_TOT (NSTAGE * STAGE_B)            // 192 KB

__device__ __forceinline__ void load_stage(uint32_t stage,
    const __half* __restrict__ Ahi, const __half* __restrict__ Alo,
    const __half* __restrict__ Bhi,
    int bm, int bn, int k0, int K, int tid)
{
    // A tiles: 128 rows x 8 chunks = 1024 -> 1 chunk/thread per tile
    {
        const int row = tid >> 3;            // 0..127
        const int kc  = tid & 7;             // 0..7
        const uint32_t sw = ((uint32_t)(row & 7)) << 4;
        const uint32_t d  = (uint32_t)row * 128 + (((uint32_t)kc * 16) ^ sw);
        const size_t g = (size_t)(bm + row) * K + k0 + kc * 8;
        CP_ASYNC16(stage + d, Ahi + g);
        CP_ASYNC16(stage + TILE_A + d, Alo + g);
    }
    // B tile: 256 rows x 8 chunks = 2048 -> 2 chunks/thread
    {
        const int brow = tid >> 2;           // 0..255
        const int kc0  = (tid & 3) * 2;      // 0,2,4,6
        const uint32_t sw  = ((uint32_t)(brow & 7)) << 4;
        const uint32_t brb = (uint32_t)brow * 128;
        const __half* pBh = Bhi + (size_t)(bn + brow) * K + k0;
        #pragma unroll
        for (int i = 0; i < 2; i++) {
            int kc = kc0 + i;
            uint32_t d = brb + (((uint32_t)kc * 16) ^ sw);
            CP_ASYNC16(stage + 2 * TILE_A + d, pBh + kc * 8);
        }
    }
}

template<bool GELU, bool OUT_SPLIT>
__global__ __launch_bounds__(1024, 1)
void gemm_f16(const __half* __restrict__ Ahi, const __half* __restrict__ Alo,
              const __half* __restrict__ Bhi,
              const float* __restrict__ bias,
              float* __restrict__ Cf,
              __half* __restrict__ Chi, __half* __restrict__ Clo,
              int M, int N, int K)
{
    extern __shared__ __align__(1024) char smem[];
    const uint32_t sb = smem_u32(smem);
    const int tid  = threadIdx.x;
    const int wid  = tid >> 5;
    const int lane = tid & 31;
    const int wr   = wid & 7;          // warp m-tile (16 rows)
    const int wc   = wid >> 3;         // warp n-tile (64 cols)
    const int bm   = blockIdx.y * BM;
    const int bn   = blockIdx.x * BN;

    float acc[8][4];                   // [pr*2+hf][4]
    #pragma unroll
    for (int b = 0; b < 8; b++)
        #pragma unroll
        for (int c = 0; c < 4; c++) acc[b][c] = 0.0f;

    // ldmatrix lane addressing
    const int amat = lane >> 3, ar = lane & 7;
    const int a_m  = wr * 16 + (amat & 1) * 8 + ar;
    const uint32_t a_kh = (uint32_t)(amat >> 1) * 16;
    const uint32_t a_rb = (uint32_t)a_m * 128;
    const uint32_t a_sx = ((uint32_t)(a_m & 7)) << 4;

    const int bmat = lane >> 3, br = lane & 7;
    const int b_n  = wc * 64 + ((bmat >> 1) << 3) + br;  // + pr*16
    const uint32_t b_kh = (uint32_t)(bmat & 1) * 16;
    const uint32_t b_rb = (uint32_t)b_n * 128;
    const uint32_t b_sx = ((uint32_t)(b_n & 7)) << 4;

    const int NT = K / BKE;

    // prologue: prefetch 2 stages
    load_stage(sb, Ahi, Alo, Bhi, bm, bn, 0, K, tid);
    CP_COMMIT();
    load_stage(sb + STAGE_B, Ahi, Alo, Bhi, bm, bn, BKE, K, tid);
    CP_COMMIT();

    for (int it = 0; it < NT; it++) {
        CP_WAIT1();
        __syncthreads();

        const uint32_t st  = sb + (it % NSTAGE) * STAGE_B;
        const uint32_t sAh = st;
        const uint32_t sAl = st + TILE_A;
        const uint32_t sBh = st + 2 * TILE_A;

        #pragma unroll
        for (int kk = 0; kk < 4; kk++) {
            // deferred gmem prefetch for stage it+2
            if (kk == 1) {
                int pf = it + 2;
                if (pf < NT)
                    load_stage(sb + (pf % NSTAGE) * STAGE_B, Ahi, Alo, Bhi,
                               bm, bn, pf * BKE, K, tid);
                CP_COMMIT();   // always commit to keep wait_group math exact
            }

            const uint32_t kb = (uint32_t)kk * 32;
            uint32_t ahi[4], alo[4];
            {
                uint32_t off = a_rb + ((kb + a_kh) ^ a_sx);
                LDSM_X4(ahi[0], ahi[1], ahi[2], ahi[3], sAh + off);
                LDSM_X4(alo[0], alo[1], alo[2], alo[3], sAl + off);
            }

            // B fragment double buffer across pr
            uint32_t bh[2][4];
            {
                uint32_t off0 = b_rb + ((kb + b_kh) ^ b_sx);
                LDSM_X4(bh[0][0], bh[0][1], bh[0][2], bh[0][3], sBh + off0);
            }
            #pragma unroll
            for (int pr = 0; pr < 4; pr++) {
                const int cur = pr & 1;
                if (pr < 3) {
                    uint32_t offn = b_rb + (pr + 1) * 2048 + ((kb + b_kh) ^ b_sx);
                    LDSM_X4(bh[cur ^ 1][0], bh[cur ^ 1][1], bh[cur ^ 1][2], bh[cur ^ 1][3],
                            sBh + offn);
                }
                // phase 1: hi * B
                MMA_FP16(acc[pr * 2 + 0], ahi, bh[cur][0], bh[cur][1]);
                MMA_FP16(acc[pr * 2 + 1], ahi, bh[cur][2], bh[cur][3]);
                // phase 2: lo * B
                MMA_FP16(acc[pr * 2 + 0], alo, bh[cur][0], bh[cur][1]);
                MMA_FP16(acc[pr * 2 + 1], alo, bh[cur][2], bh[cur][3]);
            }
        }
    }

    // epilogue
    const int mrow = bm + wr * 16 + (lane >> 2);
    const int ncol = bn + wc * 64 + (lane & 3) * 2;
    #pragma unroll
    for (int n8 = 0; n8 < 8; n8++) {
        const int n = ncol + n8 * 8;
        const float bs0 = __ldg(&bias[n]);
        const float bs1 = __ldg(&bias[n + 1]);
        #pragma unroll
        for (int hf = 0; hf < 2; hf++) {
            const int m = mrow + hf * 8;
            float v0 = acc[n8][hf * 2 + 0] + bs0;
            float v1 = acc[n8][hf * 2 + 1] + bs1;
            if (GELU) {
                v0 = 0.5f * v0 * (1.0f + erff(v0 * 0.70710678118654752440f));
                v1 = 0.5f * v1 * (1.0f + erff(v1 * 0.70710678118654752440f));
            }
            if (OUT_SPLIT) {
                __half h0 = __float2half_rn(v0);
                __half h1 = __float2half_rn(v1);
                __half l0 = __float2half_rn(v0 - __half2float(h0));
                __half l1 = __float2half_rn(v1 - __half2float(h1));
                *reinterpret_cast<__half2*>(Chi + (size_t)m * N + n) = __halves2half2(h0, h1);
                *reinterpret_cast<__half2*>(Clo + (size_t)m * N + n) = __halves2half2(l0, l1);
            } else {
                *reinterpret_cast<float2*>(Cf + (size_t)m * N + n) = make_float2(v0, v1);
            }
        }
    }
}

// ---------------------------------------------------------------------------
extern "C" void kernel_launch(void* const* d_in, const int* in_sizes, int n_in,
                              void* d_out, int out_size) {
    const float* x    = (const float*)d_in[0];
    const float* cb1  = (const float*)d_in[1];
    const int*   idx1 = (const int*)  d_in[2];
    const float* b1   = (const float*)d_in[3];
    const float* cb2  = (const float*)d_in[4];
    const int*   idx2 = (const int*)  d_in[5];
    const float* b2   = (const float*)d_in[6];
    float* out = (float*)d_out;

    __half *xhi, *xlo, *w1hi, *w2hi, *hhi, *hlo;
    cudaGetSymbolAddress((void**)&xhi,  g_xhi);
    cudaGetSymbolAddress((void**)&xlo,  g_xlo);
    cudaGetSymbolAddress((void**)&w1hi, g_w1hi);
    cudaGetSymbolAddress((void**)&w2hi, g_w2hi);
    cudaGetSymbolAddress((void**)&hhi,  g_hhi);
    cudaGetSymbolAddress((void**)&hlo,  g_hlo);

    cudaFuncSetAttribute(gemm_f16<true, true>,
                         cudaFuncAttributeMaxDynamicSharedMemorySize, SMEM_TOT);
    cudaFuncSetAttribute(gemm_f16<false, false>,
                         cudaFuncAttributeMaxDynamicSharedMemorySize, SMEM_TOT);

    {
        int n4 = (MTOK * DDIM) / 4;
        split_x_kernel<<<(n4 + 255) / 256, 256>>>(x, xhi, xlo, n4);
    }
    {
        int n4 = HDIM * (DDIM / 4);
        dequant_f16_kernel<<<(n4 + 255) / 256, 256>>>(cb1, idx1, w1hi, HDIM, DDIM / NCB);
    }
    {
        int n4 = DDIM * (HDIM / 4);
        dequant_f16_kernel<<<(n4 + 255) / 256, 256>>>(cb2, idx2, w2hi, DDIM, HDIM / NCB);
    }

    // GEMM1: h = gelu(x @ W1^T + b1), written as fp16 hi/lo
    {
        dim3 grid(HDIM / BN, MTOK / BM);     // (16, 64)
        gemm_f16<true, true><<<grid, 1024, SMEM_TOT>>>(
            xhi, xlo, w1hi, b1, nullptr, hhi, hlo, MTOK, HDIM, DDIM);
    }
    // GEMM2: out = h @ W2^T + b2 (fp32)
    {
        dim3 grid(DDIM / BN, MTOK / BM);     // (4, 64)
        gemm_f16<false, false><<<grid, 1024, SMEM_TOT>>>(
            hhi, hlo, w2hi, b2, out, nullptr, nullptr, MTOK, DDIM, HDIM);
    }
}